// round 2
// baseline (speedup 1.0000x reference)
#include <cuda_runtime.h>
#include <cuda_bf16.h>
#include <cstdint>

// Problem constants (fixed shapes from reference setup_inputs)
#define BB 32
#define CC 64
#define NN 16384          // 128*128
#define GCHUNKS 16        // N-chunks per batch for the Gram partials
#define GCN (NN / GCHUNKS) // 1024
#define KS 32             // shared-staging depth for Gram

// ---------------- scratch (device globals; no allocation allowed) ----------
__device__ float g_partial[BB * GCHUNKS * CC * CC]; // 8 MiB of partial Grams
__device__ float g_A[BB * CC * CC];                 // fused A = (gamma/sigma) * G * W
__device__ float g_scale;                           // gamma / sigma

// ---------------- f32x2 packed-FMA helpers (FFMA2, PTX-only path) ----------
__device__ __forceinline__ unsigned long long pk2(float x, float y) {
    unsigned long long r;
    asm("mov.b64 %0, {%1, %2};" : "=l"(r) : "f"(x), "f"(y));
    return r;
}
__device__ __forceinline__ void upk2(unsigned long long v, float& x, float& y) {
    asm("mov.b64 {%0, %1}, %2;" : "=f"(x), "=f"(y) : "l"(v));
}
__device__ __forceinline__ void fma2(unsigned long long& d, unsigned long long a,
                                     unsigned long long b) {
    asm("fma.rn.f32x2 %0, %1, %2, %0;" : "+l"(d) : "l"(a), "l"(b));
}

// ---------------- Kernel A: spectral norm scale ----------------------------
// v = normalize(W^T u); sigma = u2.(Wv) = ||Wv||^2 / max(||Wv||, eps)
__global__ void sigma_kernel(const float* __restrict__ W,
                             const float* __restrict__ gamma,
                             const float* __restrict__ u) {
    __shared__ float sv[CC];
    __shared__ float red[CC];
    int c = threadIdx.x; // 64 threads

    float vt = 0.f;
    #pragma unroll 8
    for (int r = 0; r < CC; r++) vt += W[r * CC + c] * u[r];
    red[c] = vt * vt;
    __syncthreads();
    if (c == 0) {
        float s = 0.f;
        for (int i = 0; i < CC; i++) s += red[i];
        red[0] = 1.f / fmaxf(sqrtf(s), 1e-12f);
    }
    __syncthreads();
    float inv = red[0];
    sv[c] = vt * inv; // v
    __syncthreads();

    float wv = 0.f;
    #pragma unroll 8
    for (int k = 0; k < CC; k++) wv += W[c * CC + k] * sv[k];
    red[c] = wv * wv;
    __syncthreads();
    if (c == 0) {
        float s2 = 0.f;
        for (int i = 0; i < CC; i++) s2 += red[i];
        float sigma = s2 / fmaxf(sqrtf(s2), 1e-12f);
        g_scale = gamma[0] / sigma;
    }
}

// ---------------- Kernel B: partial Grams G[b] = xf xf^T --------------------
// grid (GCHUNKS, BB), 256 threads. Each thread owns a 4x4 tile of the 64x64
// Gram; streams KS=32 columns at a time through shared memory.
__global__ void __launch_bounds__(256) gram_kernel(const float* __restrict__ x) {
    __shared__ float tile[KS][68]; // 68-float stride: 16B-aligned rows, spread banks
    const int tid = threadIdx.x;
    const int b = blockIdx.y;
    const int chunk = blockIdx.x;
    const float* xb = x + (size_t)b * CC * NN + (size_t)chunk * GCN;

    const int ti = tid >> 4;  // row group (4 rows)
    const int tj = tid & 15;  // col group (4 cols)

    unsigned long long acc[4][2];
    #pragma unroll
    for (int ii = 0; ii < 4; ii++) { acc[ii][0] = 0ull; acc[ii][1] = 0ull; }

    for (int ks = 0; ks < GCN; ks += KS) {
        __syncthreads();
        #pragma unroll
        for (int l = 0; l < 8; l++) {
            int idx = tid + l * 256;   // 0..2047
            int cc = idx >> 5;         // channel 0..63
            int nn = idx & 31;         // col within KS
            tile[nn][cc] = xb[(size_t)cc * NN + ks + nn];
        }
        __syncthreads();
        #pragma unroll 8
        for (int n = 0; n < KS; n++) {
            float4 rv = *(const float4*)&tile[n][4 * ti];
            ulonglong2 cp = *(const ulonglong2*)&tile[n][4 * tj]; // {c0,c1},{c2,c3}
            unsigned long long a0 = pk2(rv.x, rv.x);
            unsigned long long a1 = pk2(rv.y, rv.y);
            unsigned long long a2 = pk2(rv.z, rv.z);
            unsigned long long a3 = pk2(rv.w, rv.w);
            fma2(acc[0][0], a0, cp.x); fma2(acc[0][1], a0, cp.y);
            fma2(acc[1][0], a1, cp.x); fma2(acc[1][1], a1, cp.y);
            fma2(acc[2][0], a2, cp.x); fma2(acc[2][1], a2, cp.y);
            fma2(acc[3][0], a3, cp.x); fma2(acc[3][1], a3, cp.y);
        }
    }

    float* gp = g_partial + ((size_t)(b * GCHUNKS + chunk)) * CC * CC;
    #pragma unroll
    for (int ii = 0; ii < 4; ii++) {
        float4 o;
        upk2(acc[ii][0], o.x, o.y);
        upk2(acc[ii][1], o.z, o.w);
        *(float4*)&gp[(4 * ti + ii) * CC + 4 * tj] = o;
    }
}

// ---------------- Kernel C: A[b] = (gamma/sigma) * G[b] * W -----------------
// grid (BB), 256 threads. Reduces 16 partials, then a 64x64x64 GEMM.
__global__ void __launch_bounds__(256) afuse_kernel(const float* __restrict__ W) {
    __shared__ float Gs[CC][68];
    __shared__ float Ws[CC][68];
    const int tid = threadIdx.x;
    const int b = blockIdx.x;
    const int ti = tid >> 4;
    const int tj = tid & 15;

    float g[4][4];
    #pragma unroll
    for (int ii = 0; ii < 4; ii++)
        #pragma unroll
        for (int jj = 0; jj < 4; jj++) g[ii][jj] = 0.f;

    for (int k = 0; k < GCHUNKS; k++) {
        const float* gp = g_partial + ((size_t)(b * GCHUNKS + k)) * CC * CC;
        #pragma unroll
        for (int ii = 0; ii < 4; ii++) {
            float4 v = *(const float4*)&gp[(4 * ti + ii) * CC + 4 * tj];
            g[ii][0] += v.x; g[ii][1] += v.y; g[ii][2] += v.z; g[ii][3] += v.w;
        }
    }
    #pragma unroll
    for (int ii = 0; ii < 4; ii++)
        #pragma unroll
        for (int jj = 0; jj < 4; jj++) Gs[4 * ti + ii][4 * tj + jj] = g[ii][jj];

    #pragma unroll
    for (int l = 0; l < 16; l++) {
        int idx = tid + l * 256; // 0..4095
        Ws[idx >> 6][idx & 63] = W[idx];
    }
    __syncthreads();

    float a[4][4];
    #pragma unroll
    for (int ii = 0; ii < 4; ii++)
        #pragma unroll
        for (int jj = 0; jj < 4; jj++) a[ii][jj] = 0.f;

    for (int k = 0; k < CC; k++) {
        float4 wv = *(const float4*)&Ws[k][4 * tj];
        float g0 = Gs[4 * ti + 0][k];
        float g1 = Gs[4 * ti + 1][k];
        float g2 = Gs[4 * ti + 2][k];
        float g3 = Gs[4 * ti + 3][k];
        a[0][0] += g0 * wv.x; a[0][1] += g0 * wv.y; a[0][2] += g0 * wv.z; a[0][3] += g0 * wv.w;
        a[1][0] += g1 * wv.x; a[1][1] += g1 * wv.y; a[1][2] += g1 * wv.z; a[1][3] += g1 * wv.w;
        a[2][0] += g2 * wv.x; a[2][1] += g2 * wv.y; a[2][2] += g2 * wv.z; a[2][3] += g2 * wv.w;
        a[3][0] += g3 * wv.x; a[3][1] += g3 * wv.y; a[3][2] += g3 * wv.z; a[3][3] += g3 * wv.w;
    }

    float s = g_scale;
    float* Ab = g_A + (size_t)b * CC * CC;
    #pragma unroll
    for (int ii = 0; ii < 4; ii++)
        #pragma unroll
        for (int jj = 0; jj < 4; jj++)
            Ab[(4 * ti + ii) * CC + 4 * tj + jj] = s * a[ii][jj];
}

// ---------------- Kernel D: out = A[b] @ xf + xf ----------------------------
// grid (NN/64, BB), 256 threads. Each block: 64 rows x 64 cols of output.
__global__ void __launch_bounds__(256) out_kernel(const float* __restrict__ x,
                                                  float* __restrict__ out) {
    __shared__ float As[CC][68]; // As[c][i] = A[i][c] (transposed for float4 row reads)
    __shared__ float xs[CC][68]; // xs[c][nn]
    const int tid = threadIdx.x;
    const int b = blockIdx.y;
    const int n0 = blockIdx.x * 64;
    const float* xb = x + (size_t)b * CC * NN + n0;
    const float* Ab = g_A + (size_t)b * CC * CC;

    #pragma unroll
    for (int l = 0; l < 16; l++) {
        int idx = tid + l * 256; // 0..4095
        int i = idx >> 6;
        int c = idx & 63;
        As[c][i] = Ab[idx]; // A[i][c]
    }
    #pragma unroll
    for (int l = 0; l < 16; l++) {
        int idx = tid + l * 256;
        int c = idx >> 6;
        int nn = idx & 63;
        xs[c][nn] = xb[(size_t)c * NN + nn];
    }
    __syncthreads();

    const int ti = tid >> 4; // row group (4 rows)
    const int tn = tid & 15; // col group (4 cols)

    unsigned long long acc[4][2];
    #pragma unroll
    for (int ii = 0; ii < 4; ii++) { acc[ii][0] = 0ull; acc[ii][1] = 0ull; }

    #pragma unroll 8
    for (int k = 0; k < CC; k++) {
        float4 av = *(const float4*)&As[k][4 * ti];          // A[4ti..+3][k]
        ulonglong2 xp = *(const ulonglong2*)&xs[k][4 * tn];  // {x0,x1},{x2,x3}
        unsigned long long a0 = pk2(av.x, av.x);
        unsigned long long a1 = pk2(av.y, av.y);
        unsigned long long a2 = pk2(av.z, av.z);
        unsigned long long a3 = pk2(av.w, av.w);
        fma2(acc[0][0], a0, xp.x); fma2(acc[0][1], a0, xp.y);
        fma2(acc[1][0], a1, xp.x); fma2(acc[1][1], a1, xp.y);
        fma2(acc[2][0], a2, xp.x); fma2(acc[2][1], a2, xp.y);
        fma2(acc[3][0], a3, xp.x); fma2(acc[3][1], a3, xp.y);
    }

    #pragma unroll
    for (int ii = 0; ii < 4; ii++) {
        int row = 4 * ti + ii;
        float4 xadd = *(const float4*)&xs[row][4 * tn];
        float4 o;
        upk2(acc[ii][0], o.x, o.y);
        upk2(acc[ii][1], o.z, o.w);
        o.x += xadd.x; o.y += xadd.y; o.z += xadd.z; o.w += xadd.w;
        *(float4*)&out[(size_t)b * CC * NN + (size_t)row * NN + n0 + 4 * tn] = o;
    }
}

// ---------------- launch ----------------------------------------------------
extern "C" void kernel_launch(void* const* d_in, const int* in_sizes, int n_in,
                              void* d_out, int out_size) {
    const float* x     = (const float*)d_in[0]; // [32,64,128,128]
    const float* W     = (const float*)d_in[1]; // [64,64]
    const float* gamma = (const float*)d_in[2]; // [1]
    const float* u     = (const float*)d_in[3]; // [64]
    float* out = (float*)d_out;

    sigma_kernel<<<1, 64>>>(W, gamma, u);

    dim3 gb(GCHUNKS, BB);
    gram_kernel<<<gb, 256>>>(x);

    afuse_kernel<<<BB, 256>>>(W);

    dim3 gd(NN / 64, BB);
    out_kernel<<<gd, 256>>>(x, out);
}

// round 4
// speedup vs baseline: 1.1461x; 1.1461x over previous
#include <cuda_runtime.h>
#include <cuda_bf16.h>
#include <cstdint>

// Problem constants (fixed shapes from reference setup_inputs)
#define BB 32
#define CC 64
#define NN 16384           // 128*128
#define GCHUNKS 32         // N-chunks per batch for the Gram partials
#define GCN (NN / GCHUNKS) // 512
#define KS 16              // shared-staging depth for Gram

// ---------------- scratch (device globals; no allocation allowed) ----------
__device__ float g_partial[BB * GCHUNKS * CC * CC]; // 16 MiB of partial Grams
__device__ float g_A[BB * CC * CC];                 // fused A = (gamma/sigma) * G * W
__device__ float g_scale;                           // gamma / sigma

// ---------------- f32x2 packed-FMA helpers (FFMA2, PTX-only path) ----------
__device__ __forceinline__ unsigned long long pk2(float x, float y) {
    unsigned long long r;
    asm("mov.b64 %0, {%1, %2};" : "=l"(r) : "f"(x), "f"(y));
    return r;
}
__device__ __forceinline__ void upk2(unsigned long long v, float& x, float& y) {
    asm("mov.b64 {%0, %1}, %2;" : "=f"(x), "=f"(y) : "l"(v));
}
__device__ __forceinline__ void fma2(unsigned long long& d, unsigned long long a,
                                     unsigned long long b) {
    asm("fma.rn.f32x2 %0, %1, %2, %0;" : "+l"(d) : "l"(a), "l"(b));
}

// ---------------- Kernel A: spectral norm scale ----------------------------
__global__ void sigma_kernel(const float* __restrict__ W,
                             const float* __restrict__ gamma,
                             const float* __restrict__ u) {
    __shared__ float sv[CC];
    __shared__ float red[CC];
    int c = threadIdx.x; // 64 threads

    float vt = 0.f;
    #pragma unroll 8
    for (int r = 0; r < CC; r++) vt += W[r * CC + c] * u[r];
    red[c] = vt * vt;
    __syncthreads();
    if (c == 0) {
        float s = 0.f;
        for (int i = 0; i < CC; i++) s += red[i];
        red[0] = 1.f / fmaxf(sqrtf(s), 1e-12f);
    }
    __syncthreads();
    float inv = red[0];
    sv[c] = vt * inv; // v
    __syncthreads();

    float wv = 0.f;
    #pragma unroll 8
    for (int k = 0; k < CC; k++) wv += W[c * CC + k] * sv[k];
    red[c] = wv * wv;
    __syncthreads();
    if (c == 0) {
        float s2 = 0.f;
        for (int i = 0; i < CC; i++) s2 += red[i];
        float sigma = s2 / fmaxf(sqrtf(s2), 1e-12f);
        g_scale = gamma[0] / sigma;
    }
}

// ---------------- Kernel B: partial Grams G[b] = xf xf^T --------------------
// grid (GCHUNKS, BB), 64 threads. Each thread owns an 8x8 tile of the 64x64
// Gram (f32x2-packed cols); streams KS=16 columns through shared memory.
// Lane map: ti=tid>>3 rows-group (8 lanes share row reads), tj=tid&7 cols.
__global__ void __launch_bounds__(64) gram_kernel(const float* __restrict__ x) {
    __shared__ float tile[KS][68];
    const int tid = threadIdx.x;
    const int b = blockIdx.y;
    const int chunk = blockIdx.x;
    const float* xb = x + (size_t)b * CC * NN + (size_t)chunk * GCN;

    const int ti = tid >> 3; // rows 8ti .. 8ti+7
    const int tj = tid & 7;  // cols 8tj .. 8tj+7

    unsigned long long acc[8][4];
    #pragma unroll
    for (int i = 0; i < 8; i++)
        #pragma unroll
        for (int j = 0; j < 4; j++) acc[i][j] = 0ull;

    for (int ks = 0; ks < GCN; ks += KS) {
        __syncthreads();
        // stage KS x 64 (transposed): tile[n][cc]
        #pragma unroll
        for (int l = 0; l < 16; l++) {
            int idx = tid + l * 64;    // 0..1023
            int n = idx & 15;
            int cc = idx >> 4;         // 0..63
            tile[n][cc] = xb[(size_t)cc * NN + ks + n];
        }
        __syncthreads();
        #pragma unroll 8
        for (int n = 0; n < KS; n++) {
            float4 r0 = *(const float4*)&tile[n][8 * ti];
            float4 r1 = *(const float4*)&tile[n][8 * ti + 4];
            ulonglong2 c0 = *(const ulonglong2*)&tile[n][8 * tj];
            ulonglong2 c1 = *(const ulonglong2*)&tile[n][8 * tj + 4];
            unsigned long long a0 = pk2(r0.x, r0.x);
            unsigned long long a1 = pk2(r0.y, r0.y);
            unsigned long long a2 = pk2(r0.z, r0.z);
            unsigned long long a3 = pk2(r0.w, r0.w);
            unsigned long long a4 = pk2(r1.x, r1.x);
            unsigned long long a5 = pk2(r1.y, r1.y);
            unsigned long long a6 = pk2(r1.z, r1.z);
            unsigned long long a7 = pk2(r1.w, r1.w);
            fma2(acc[0][0], a0, c0.x); fma2(acc[0][1], a0, c0.y);
            fma2(acc[0][2], a0, c1.x); fma2(acc[0][3], a0, c1.y);
            fma2(acc[1][0], a1, c0.x); fma2(acc[1][1], a1, c0.y);
            fma2(acc[1][2], a1, c1.x); fma2(acc[1][3], a1, c1.y);
            fma2(acc[2][0], a2, c0.x); fma2(acc[2][1], a2, c0.y);
            fma2(acc[2][2], a2, c1.x); fma2(acc[2][3], a2, c1.y);
            fma2(acc[3][0], a3, c0.x); fma2(acc[3][1], a3, c0.y);
            fma2(acc[3][2], a3, c1.x); fma2(acc[3][3], a3, c1.y);
            fma2(acc[4][0], a4, c0.x); fma2(acc[4][1], a4, c0.y);
            fma2(acc[4][2], a4, c1.x); fma2(acc[4][3], a4, c1.y);
            fma2(acc[5][0], a5, c0.x); fma2(acc[5][1], a5, c0.y);
            fma2(acc[5][2], a5, c1.x); fma2(acc[5][3], a5, c1.y);
            fma2(acc[6][0], a6, c0.x); fma2(acc[6][1], a6, c0.y);
            fma2(acc[6][2], a6, c1.x); fma2(acc[6][3], a6, c1.y);
            fma2(acc[7][0], a7, c0.x); fma2(acc[7][1], a7, c0.y);
            fma2(acc[7][2], a7, c1.x); fma2(acc[7][3], a7, c1.y);
        }
    }

    float* gp = g_partial + ((size_t)(b * GCHUNKS + chunk)) * CC * CC;
    #pragma unroll
    for (int i = 0; i < 8; i++) {
        float4 o0, o1;
        upk2(acc[i][0], o0.x, o0.y);
        upk2(acc[i][1], o0.z, o0.w);
        upk2(acc[i][2], o1.x, o1.y);
        upk2(acc[i][3], o1.z, o1.w);
        *(float4*)&gp[(8 * ti + i) * CC + 8 * tj]     = o0;
        *(float4*)&gp[(8 * ti + i) * CC + 8 * tj + 4] = o1;
    }
}

// ---------------- Kernel C: A[b] = (gamma/sigma) * G[b] * W -----------------
__global__ void __launch_bounds__(256) afuse_kernel(const float* __restrict__ W) {
    __shared__ float Gs[CC][68];
    __shared__ float Ws[CC][68];
    const int tid = threadIdx.x;
    const int b = blockIdx.x;
    const int ti = tid >> 4;
    const int tj = tid & 15;

    float g[4][4];
    #pragma unroll
    for (int ii = 0; ii < 4; ii++)
        #pragma unroll
        for (int jj = 0; jj < 4; jj++) g[ii][jj] = 0.f;

    for (int k = 0; k < GCHUNKS; k++) {
        const float* gp = g_partial + ((size_t)(b * GCHUNKS + k)) * CC * CC;
        #pragma unroll
        for (int ii = 0; ii < 4; ii++) {
            float4 v = *(const float4*)&gp[(4 * ti + ii) * CC + 4 * tj];
            g[ii][0] += v.x; g[ii][1] += v.y; g[ii][2] += v.z; g[ii][3] += v.w;
        }
    }
    #pragma unroll
    for (int ii = 0; ii < 4; ii++)
        #pragma unroll
        for (int jj = 0; jj < 4; jj++) Gs[4 * ti + ii][4 * tj + jj] = g[ii][jj];

    #pragma unroll
    for (int l = 0; l < 16; l++) {
        int idx = tid + l * 256; // 0..4095
        Ws[idx >> 6][idx & 63] = W[idx];
    }
    __syncthreads();

    float a[4][4];
    #pragma unroll
    for (int ii = 0; ii < 4; ii++)
        #pragma unroll
        for (int jj = 0; jj < 4; jj++) a[ii][jj] = 0.f;

    for (int k = 0; k < CC; k++) {
        float4 wv = *(const float4*)&Ws[k][4 * tj];
        float g0 = Gs[4 * ti + 0][k];
        float g1 = Gs[4 * ti + 1][k];
        float g2 = Gs[4 * ti + 2][k];
        float g3 = Gs[4 * ti + 3][k];
        a[0][0] += g0 * wv.x; a[0][1] += g0 * wv.y; a[0][2] += g0 * wv.z; a[0][3] += g0 * wv.w;
        a[1][0] += g1 * wv.x; a[1][1] += g1 * wv.y; a[1][2] += g1 * wv.z; a[1][3] += g1 * wv.w;
        a[2][0] += g2 * wv.x; a[2][1] += g2 * wv.y; a[2][2] += g2 * wv.z; a[2][3] += g2 * wv.w;
        a[3][0] += g3 * wv.x; a[3][1] += g3 * wv.y; a[3][2] += g3 * wv.z; a[3][3] += g3 * wv.w;
    }

    float s = g_scale;
    float* Ab = g_A + (size_t)b * CC * CC;
    #pragma unroll
    for (int ii = 0; ii < 4; ii++)
        #pragma unroll
        for (int jj = 0; jj < 4; jj++)
            Ab[(4 * ti + ii) * CC + 4 * tj + jj] = s * a[ii][jj];
}

// ---------------- Kernel D: out = A[b] @ xf + xf ----------------------------
// grid (NN/128, BB), 128 threads. Block tile 64 rows x 128 cols.
// Thread tile 8 rows x 8 cols (f32x2 packed). A transposed in smem so the
// per-k A column is contiguous; 16 lanes share each A address (broadcast).
__global__ void __launch_bounds__(128) out_kernel(const float* __restrict__ x,
                                                  float* __restrict__ out) {
    __shared__ float As[CC][68];  // As[k][i] = A[i][k]
    __shared__ float xs[CC][132]; // xs[c][n], 128 cols + pad
    const int tid = threadIdx.x;
    const int b = blockIdx.y;
    const int n0 = blockIdx.x * 128;
    const float* xb = x + (size_t)b * CC * NN + n0;
    const float* Ab = g_A + (size_t)b * CC * CC;

    // load A transposed: 4096 floats / 128 threads = 32 each
    #pragma unroll
    for (int l = 0; l < 32; l++) {
        int idx = tid + l * 128; // 0..4095
        int i = idx >> 6;
        int c = idx & 63;
        As[c][i] = Ab[idx];
    }
    // load xs: 64 x 128 floats via float4 (2048 f4 / 128 threads = 16 each)
    #pragma unroll
    for (int l = 0; l < 16; l++) {
        int idx = tid + l * 128; // 0..2047
        int c = idx >> 5;        // 0..63
        int n4 = (idx & 31) * 4; // 0..124
        float4 v = *(const float4*)&xb[(size_t)c * NN + n4];
        *(float4*)&xs[c][n4] = v;
    }
    __syncthreads();

    const int ti = tid >> 4; // 0..7 -> rows 8ti..8ti+7
    const int tj = tid & 15; // 0..15 -> cols 8tj..8tj+7

    unsigned long long acc[8][4];
    #pragma unroll
    for (int i = 0; i < 8; i++)
        #pragma unroll
        for (int j = 0; j < 4; j++) acc[i][j] = 0ull;

    #pragma unroll 8
    for (int k = 0; k < CC; k++) {
        float4 av0 = *(const float4*)&As[k][8 * ti];
        float4 av1 = *(const float4*)&As[k][8 * ti + 4];
        ulonglong2 x0 = *(const ulonglong2*)&xs[k][8 * tj];
        ulonglong2 x1 = *(const ulonglong2*)&xs[k][8 * tj + 4];
        unsigned long long a0 = pk2(av0.x, av0.x);
        unsigned long long a1 = pk2(av0.y, av0.y);
        unsigned long long a2 = pk2(av0.z, av0.z);
        unsigned long long a3 = pk2(av0.w, av0.w);
        unsigned long long a4 = pk2(av1.x, av1.x);
        unsigned long long a5 = pk2(av1.y, av1.y);
        unsigned long long a6 = pk2(av1.z, av1.z);
        unsigned long long a7 = pk2(av1.w, av1.w);
        fma2(acc[0][0], a0, x0.x); fma2(acc[0][1], a0, x0.y);
        fma2(acc[0][2], a0, x1.x); fma2(acc[0][3], a0, x1.y);
        fma2(acc[1][0], a1, x0.x); fma2(acc[1][1], a1, x0.y);
        fma2(acc[1][2], a1, x1.x); fma2(acc[1][3], a1, x1.y);
        fma2(acc[2][0], a2, x0.x); fma2(acc[2][1], a2, x0.y);
        fma2(acc[2][2], a2, x1.x); fma2(acc[2][3], a2, x1.y);
        fma2(acc[3][0], a3, x0.x); fma2(acc[3][1], a3, x0.y);
        fma2(acc[3][2], a3, x1.x); fma2(acc[3][3], a3, x1.y);
        fma2(acc[4][0], a4, x0.x); fma2(acc[4][1], a4, x0.y);
        fma2(acc[4][2], a4, x1.x); fma2(acc[4][3], a4, x1.y);
        fma2(acc[5][0], a5, x0.x); fma2(acc[5][1], a5, x0.y);
        fma2(acc[5][2], a5, x1.x); fma2(acc[5][3], a5, x1.y);
        fma2(acc[6][0], a6, x0.x); fma2(acc[6][1], a6, x0.y);
        fma2(acc[6][2], a6, x1.x); fma2(acc[6][3], a6, x1.y);
        fma2(acc[7][0], a7, x0.x); fma2(acc[7][1], a7, x0.y);
        fma2(acc[7][2], a7, x1.x); fma2(acc[7][3], a7, x1.y);
    }

    // epilogue: add residual x, store
    #pragma unroll
    for (int i = 0; i < 8; i++) {
        int row = 8 * ti + i;
        float4 xa0 = *(const float4*)&xs[row][8 * tj];
        float4 xa1 = *(const float4*)&xs[row][8 * tj + 4];
        float4 o0, o1;
        upk2(acc[i][0], o0.x, o0.y);
        upk2(acc[i][1], o0.z, o0.w);
        upk2(acc[i][2], o1.x, o1.y);
        upk2(acc[i][3], o1.z, o1.w);
        o0.x += xa0.x; o0.y += xa0.y; o0.z += xa0.z; o0.w += xa0.w;
        o1.x += xa1.x; o1.y += xa1.y; o1.z += xa1.z; o1.w += xa1.w;
        float* op = out + (size_t)b * CC * NN + (size_t)row * NN + n0 + 8 * tj;
        *(float4*)&op[0] = o0;
        *(float4*)&op[4] = o1;
    }
}

// ---------------- launch ----------------------------------------------------
extern "C" void kernel_launch(void* const* d_in, const int* in_sizes, int n_in,
                              void* d_out, int out_size) {
    const float* x     = (const float*)d_in[0]; // [32,64,128,128]
    const float* W     = (const float*)d_in[1]; // [64,64]
    const float* gamma = (const float*)d_in[2]; // [1]
    const float* u     = (const float*)d_in[3]; // [64]
    float* out = (float*)d_out;

    sigma_kernel<<<1, 64>>>(W, gamma, u);

    dim3 gb(GCHUNKS, BB);
    gram_kernel<<<gb, 64>>>(x);

    afuse_kernel<<<BB, 256>>>(W);

    dim3 gd(NN / 128, BB);
    out_kernel<<<gd, 128>>>(x, out);
}

// round 5
// speedup vs baseline: 1.2851x; 1.1213x over previous
#include <cuda_runtime.h>
#include <cuda_bf16.h>
#include <cstdint>

// Problem constants (fixed shapes from reference setup_inputs)
#define BB 32
#define CC 64
#define NN 16384           // 128*128
#define GCHUNKS 32         // N-chunks per batch for the Gram partials
#define GCN (NN / GCHUNKS) // 512
#define KS 16              // shared-staging depth for Gram

// ---------------- scratch (device globals; no allocation allowed) ----------
__device__ float g_partial[BB * GCHUNKS * CC * CC]; // 16 MiB of partial Grams
__device__ float g_A[BB * CC * CC];                 // fused A = (gamma/sigma) * G * W
__device__ float g_scale;                           // gamma / sigma

// ---------------- f32x2 packed-FMA helpers (FFMA2, PTX-only path) ----------
__device__ __forceinline__ unsigned long long pk2(float x, float y) {
    unsigned long long r;
    asm("mov.b64 %0, {%1, %2};" : "=l"(r) : "f"(x), "f"(y));
    return r;
}
__device__ __forceinline__ void upk2(unsigned long long v, float& x, float& y) {
    asm("mov.b64 {%0, %1}, %2;" : "=f"(x), "=f"(y) : "l"(v));
}
__device__ __forceinline__ void fma2(unsigned long long& d, unsigned long long a,
                                     unsigned long long b) {
    asm("fma.rn.f32x2 %0, %1, %2, %0;" : "+l"(d) : "l"(a), "l"(b));
}

// ---------------- Kernel A: spectral norm scale ----------------------------
__global__ void sigma_kernel(const float* __restrict__ W,
                             const float* __restrict__ gamma,
                             const float* __restrict__ u) {
    __shared__ float sv[CC];
    __shared__ float red[CC];
    int c = threadIdx.x; // 64 threads

    float vt = 0.f;
    #pragma unroll 8
    for (int r = 0; r < CC; r++) vt += W[r * CC + c] * u[r];
    red[c] = vt * vt;
    __syncthreads();
    if (c == 0) {
        float s = 0.f;
        for (int i = 0; i < CC; i++) s += red[i];
        red[0] = 1.f / fmaxf(sqrtf(s), 1e-12f);
    }
    __syncthreads();
    float inv = red[0];
    sv[c] = vt * inv; // v
    __syncthreads();

    float wv = 0.f;
    #pragma unroll 8
    for (int k = 0; k < CC; k++) wv += W[c * CC + k] * sv[k];
    red[c] = wv * wv;
    __syncthreads();
    if (c == 0) {
        float s2 = 0.f;
        for (int i = 0; i < CC; i++) s2 += red[i];
        float sigma = s2 / fmaxf(sqrtf(s2), 1e-12f);
        g_scale = gamma[0] / sigma;
    }
}

// ---------------- Kernel B: partial Grams G[b] = xf xf^T --------------------
// grid (GCHUNKS, BB), 64 threads. Each thread owns 8 rows x (4+4) cols of the
// 64x64 Gram: cols [4tj..4tj+3] and [4tj+32..4tj+35]. Column loads are DENSE
// across the warp (16B stride) -> minimal LDS wavefronts.
__global__ void __launch_bounds__(64) gram_kernel(const float* __restrict__ x) {
    __shared__ float tile[KS][68];
    const int tid = threadIdx.x;
    const int b = blockIdx.y;
    const int chunk = blockIdx.x;
    const float* xb = x + (size_t)b * CC * NN + (size_t)chunk * GCN;

    const int ti = tid >> 3; // rows 8ti .. 8ti+7
    const int tj = tid & 7;  // cols 4tj..4tj+3 and 4tj+32..4tj+35

    unsigned long long acc[8][4];
    #pragma unroll
    for (int i = 0; i < 8; i++)
        #pragma unroll
        for (int j = 0; j < 4; j++) acc[i][j] = 0ull;

    for (int ks = 0; ks < GCN; ks += KS) {
        __syncthreads();
        // stage KS x 64 (transposed): tile[n][cc]
        #pragma unroll
        for (int l = 0; l < 16; l++) {
            int idx = tid + l * 64;    // 0..1023
            int n = idx & 15;
            int cc = idx >> 4;         // 0..63
            tile[n][cc] = xb[(size_t)cc * NN + ks + n];
        }
        __syncthreads();
        #pragma unroll 8
        for (int n = 0; n < KS; n++) {
            float4 r0 = *(const float4*)&tile[n][8 * ti];
            float4 r1 = *(const float4*)&tile[n][8 * ti + 4];
            ulonglong2 c0 = *(const ulonglong2*)&tile[n][4 * tj];      // dense
            ulonglong2 c1 = *(const ulonglong2*)&tile[n][4 * tj + 32]; // dense
            unsigned long long a0 = pk2(r0.x, r0.x);
            unsigned long long a1 = pk2(r0.y, r0.y);
            unsigned long long a2 = pk2(r0.z, r0.z);
            unsigned long long a3 = pk2(r0.w, r0.w);
            unsigned long long a4 = pk2(r1.x, r1.x);
            unsigned long long a5 = pk2(r1.y, r1.y);
            unsigned long long a6 = pk2(r1.z, r1.z);
            unsigned long long a7 = pk2(r1.w, r1.w);
            fma2(acc[0][0], a0, c0.x); fma2(acc[0][1], a0, c0.y);
            fma2(acc[0][2], a0, c1.x); fma2(acc[0][3], a0, c1.y);
            fma2(acc[1][0], a1, c0.x); fma2(acc[1][1], a1, c0.y);
            fma2(acc[1][2], a1, c1.x); fma2(acc[1][3], a1, c1.y);
            fma2(acc[2][0], a2, c0.x); fma2(acc[2][1], a2, c0.y);
            fma2(acc[2][2], a2, c1.x); fma2(acc[2][3], a2, c1.y);
            fma2(acc[3][0], a3, c0.x); fma2(acc[3][1], a3, c0.y);
            fma2(acc[3][2], a3, c1.x); fma2(acc[3][3], a3, c1.y);
            fma2(acc[4][0], a4, c0.x); fma2(acc[4][1], a4, c0.y);
            fma2(acc[4][2], a4, c1.x); fma2(acc[4][3], a4, c1.y);
            fma2(acc[5][0], a5, c0.x); fma2(acc[5][1], a5, c0.y);
            fma2(acc[5][2], a5, c1.x); fma2(acc[5][3], a5, c1.y);
            fma2(acc[6][0], a6, c0.x); fma2(acc[6][1], a6, c0.y);
            fma2(acc[6][2], a6, c1.x); fma2(acc[6][3], a6, c1.y);
            fma2(acc[7][0], a7, c0.x); fma2(acc[7][1], a7, c0.y);
            fma2(acc[7][2], a7, c1.x); fma2(acc[7][3], a7, c1.y);
        }
    }

    float* gp = g_partial + ((size_t)(b * GCHUNKS + chunk)) * CC * CC;
    #pragma unroll
    for (int i = 0; i < 8; i++) {
        float4 o0, o1;
        upk2(acc[i][0], o0.x, o0.y);
        upk2(acc[i][1], o0.z, o0.w);
        upk2(acc[i][2], o1.x, o1.y);
        upk2(acc[i][3], o1.z, o1.w);
        *(float4*)&gp[(8 * ti + i) * CC + 4 * tj]      = o0;
        *(float4*)&gp[(8 * ti + i) * CC + 4 * tj + 32] = o1;
    }
}

// ---------------- Kernel C: A[b] = (gamma/sigma) * G[b] * W -----------------
__global__ void __launch_bounds__(256) afuse_kernel(const float* __restrict__ W) {
    __shared__ float Gs[CC][68];
    __shared__ float Ws[CC][68];
    const int tid = threadIdx.x;
    const int b = blockIdx.x;
    const int ti = tid >> 4;
    const int tj = tid & 15;

    float g[4][4];
    #pragma unroll
    for (int ii = 0; ii < 4; ii++)
        #pragma unroll
        for (int jj = 0; jj < 4; jj++) g[ii][jj] = 0.f;

    for (int k = 0; k < GCHUNKS; k++) {
        const float* gp = g_partial + ((size_t)(b * GCHUNKS + k)) * CC * CC;
        #pragma unroll
        for (int ii = 0; ii < 4; ii++) {
            float4 v = *(const float4*)&gp[(4 * ti + ii) * CC + 4 * tj];
            g[ii][0] += v.x; g[ii][1] += v.y; g[ii][2] += v.z; g[ii][3] += v.w;
        }
    }
    #pragma unroll
    for (int ii = 0; ii < 4; ii++)
        #pragma unroll
        for (int jj = 0; jj < 4; jj++) Gs[4 * ti + ii][4 * tj + jj] = g[ii][jj];

    #pragma unroll
    for (int l = 0; l < 16; l++) {
        int idx = tid + l * 256; // 0..4095
        Ws[idx >> 6][idx & 63] = W[idx];
    }
    __syncthreads();

    float a[4][4];
    #pragma unroll
    for (int ii = 0; ii < 4; ii++)
        #pragma unroll
        for (int jj = 0; jj < 4; jj++) a[ii][jj] = 0.f;

    for (int k = 0; k < CC; k++) {
        float4 wv = *(const float4*)&Ws[k][4 * tj];
        float g0 = Gs[4 * ti + 0][k];
        float g1 = Gs[4 * ti + 1][k];
        float g2 = Gs[4 * ti + 2][k];
        float g3 = Gs[4 * ti + 3][k];
        a[0][0] += g0 * wv.x; a[0][1] += g0 * wv.y; a[0][2] += g0 * wv.z; a[0][3] += g0 * wv.w;
        a[1][0] += g1 * wv.x; a[1][1] += g1 * wv.y; a[1][2] += g1 * wv.z; a[1][3] += g1 * wv.w;
        a[2][0] += g2 * wv.x; a[2][1] += g2 * wv.y; a[2][2] += g2 * wv.z; a[2][3] += g2 * wv.w;
        a[3][0] += g3 * wv.x; a[3][1] += g3 * wv.y; a[3][2] += g3 * wv.z; a[3][3] += g3 * wv.w;
    }

    float s = g_scale;
    float* Ab = g_A + (size_t)b * CC * CC;
    #pragma unroll
    for (int ii = 0; ii < 4; ii++)
        #pragma unroll
        for (int jj = 0; jj < 4; jj++)
            Ab[(4 * ti + ii) * CC + 4 * tj + jj] = s * a[ii][jj];
}

// ---------------- Kernel D: out = A[b] @ xf + xf ----------------------------
// grid (NN/128, BB), 128 threads. Block tile 64 rows x 128 cols.
// Thread tile: 8 rows x (4+4) cols: [4tj..4tj+3] and [4tj+64..4tj+67].
// x-loads are DENSE across the 16 tj lanes (16B stride) -> 2 wavefronts each.
__global__ void __launch_bounds__(128) out_kernel(const float* __restrict__ x,
                                                  float* __restrict__ out) {
    __shared__ float As[CC][68];  // As[k][i] = A[i][k]
    __shared__ float xs[CC][132]; // xs[c][n], 128 cols + pad
    const int tid = threadIdx.x;
    const int b = blockIdx.y;
    const int n0 = blockIdx.x * 128;
    const float* xb = x + (size_t)b * CC * NN + n0;
    const float* Ab = g_A + (size_t)b * CC * CC;

    // load A transposed: 4096 floats / 128 threads = 32 each
    #pragma unroll
    for (int l = 0; l < 32; l++) {
        int idx = tid + l * 128; // 0..4095
        int i = idx >> 6;
        int c = idx & 63;
        As[c][i] = Ab[idx];
    }
    // load xs: 64 x 128 floats via float4 (2048 f4 / 128 threads = 16 each)
    #pragma unroll
    for (int l = 0; l < 16; l++) {
        int idx = tid + l * 128; // 0..2047
        int c = idx >> 5;        // 0..63
        int n4 = (idx & 31) * 4; // 0..124
        float4 v = *(const float4*)&xb[(size_t)c * NN + n4];
        *(float4*)&xs[c][n4] = v;
    }
    __syncthreads();

    const int ti = tid >> 4; // 0..7 -> rows 8ti..8ti+7
    const int tj = tid & 15; // 0..15 -> cols 4tj..4tj+3 and 4tj+64..+67

    unsigned long long acc[8][4];
    #pragma unroll
    for (int i = 0; i < 8; i++)
        #pragma unroll
        for (int j = 0; j < 4; j++) acc[i][j] = 0ull;

    #pragma unroll 8
    for (int k = 0; k < CC; k++) {
        float4 av0 = *(const float4*)&As[k][8 * ti];
        float4 av1 = *(const float4*)&As[k][8 * ti + 4];
        ulonglong2 x0 = *(const ulonglong2*)&xs[k][4 * tj];      // dense 256B
        ulonglong2 x1 = *(const ulonglong2*)&xs[k][4 * tj + 64]; // dense 256B
        unsigned long long a0 = pk2(av0.x, av0.x);
        unsigned long long a1 = pk2(av0.y, av0.y);
        unsigned long long a2 = pk2(av0.z, av0.z);
        unsigned long long a3 = pk2(av0.w, av0.w);
        unsigned long long a4 = pk2(av1.x, av1.x);
        unsigned long long a5 = pk2(av1.y, av1.y);
        unsigned long long a6 = pk2(av1.z, av1.z);
        unsigned long long a7 = pk2(av1.w, av1.w);
        fma2(acc[0][0], a0, x0.x); fma2(acc[0][1], a0, x0.y);
        fma2(acc[0][2], a0, x1.x); fma2(acc[0][3], a0, x1.y);
        fma2(acc[1][0], a1, x0.x); fma2(acc[1][1], a1, x0.y);
        fma2(acc[1][2], a1, x1.x); fma2(acc[1][3], a1, x1.y);
        fma2(acc[2][0], a2, x0.x); fma2(acc[2][1], a2, x0.y);
        fma2(acc[2][2], a2, x1.x); fma2(acc[2][3], a2, x1.y);
        fma2(acc[3][0], a3, x0.x); fma2(acc[3][1], a3, x0.y);
        fma2(acc[3][2], a3, x1.x); fma2(acc[3][3], a3, x1.y);
        fma2(acc[4][0], a4, x0.x); fma2(acc[4][1], a4, x0.y);
        fma2(acc[4][2], a4, x1.x); fma2(acc[4][3], a4, x1.y);
        fma2(acc[5][0], a5, x0.x); fma2(acc[5][1], a5, x0.y);
        fma2(acc[5][2], a5, x1.x); fma2(acc[5][3], a5, x1.y);
        fma2(acc[6][0], a6, x0.x); fma2(acc[6][1], a6, x0.y);
        fma2(acc[6][2], a6, x1.x); fma2(acc[6][3], a6, x1.y);
        fma2(acc[7][0], a7, x0.x); fma2(acc[7][1], a7, x0.y);
        fma2(acc[7][2], a7, x1.x); fma2(acc[7][3], a7, x1.y);
    }

    // epilogue: add residual x, store (dense float4 stores across lanes)
    #pragma unroll
    for (int i = 0; i < 8; i++) {
        int row = 8 * ti + i;
        float4 xa0 = *(const float4*)&xs[row][4 * tj];
        float4 xa1 = *(const float4*)&xs[row][4 * tj + 64];
        float4 o0, o1;
        upk2(acc[i][0], o0.x, o0.y);
        upk2(acc[i][1], o0.z, o0.w);
        upk2(acc[i][2], o1.x, o1.y);
        upk2(acc[i][3], o1.z, o1.w);
        o0.x += xa0.x; o0.y += xa0.y; o0.z += xa0.z; o0.w += xa0.w;
        o1.x += xa1.x; o1.y += xa1.y; o1.z += xa1.z; o1.w += xa1.w;
        float* op = out + (size_t)b * CC * NN + (size_t)row * NN + n0;
        *(float4*)&op[4 * tj]      = o0;
        *(float4*)&op[4 * tj + 64] = o1;
    }
}

// ---------------- launch ----------------------------------------------------
extern "C" void kernel_launch(void* const* d_in, const int* in_sizes, int n_in,
                              void* d_out, int out_size) {
    const float* x     = (const float*)d_in[0]; // [32,64,128,128]
    const float* W     = (const float*)d_in[1]; // [64,64]
    const float* gamma = (const float*)d_in[2]; // [1]
    const float* u     = (const float*)d_in[3]; // [64]
    float* out = (float*)d_out;

    sigma_kernel<<<1, 64>>>(W, gamma, u);

    dim3 gb(GCHUNKS, BB);
    gram_kernel<<<gb, 64>>>(x);

    afuse_kernel<<<BB, 256>>>(W);

    dim3 gd(NN / 128, BB);
    out_kernel<<<gd, 128>>>(x, out);
}

// round 6
// speedup vs baseline: 1.2949x; 1.0076x over previous
#include <cuda_runtime.h>
#include <cuda_bf16.h>
#include <cstdint>

// Problem constants (fixed shapes from reference setup_inputs)
#define BB 32
#define CC 64
#define NN 16384           // 128*128
#define GCHUNKS 32         // N-chunks per batch for the Gram partials
#define GCN (NN / GCHUNKS) // 512
#define KS 16              // shared-staging depth for Gram

// ---------------- scratch (device globals; no allocation allowed) ----------
__device__ float g_partial[BB * GCHUNKS * CC * CC]; // 16 MiB of partial Grams
__device__ float g_A[BB * CC * CC];                 // fused A = (gamma/sigma) * G * W
__device__ float g_scale;                           // gamma / sigma

// ---------------- f32x2 packed-FMA helpers (FFMA2, PTX-only path) ----------
__device__ __forceinline__ unsigned long long pk2(float x, float y) {
    unsigned long long r;
    asm("mov.b64 %0, {%1, %2};" : "=l"(r) : "f"(x), "f"(y));
    return r;
}
__device__ __forceinline__ void upk2(unsigned long long v, float& x, float& y) {
    asm("mov.b64 {%0, %1}, %2;" : "=f"(x), "=f"(y) : "l"(v));
}
__device__ __forceinline__ void fma2(unsigned long long& d, unsigned long long a,
                                     unsigned long long b) {
    asm("fma.rn.f32x2 %0, %1, %2, %0;" : "+l"(d) : "l"(a), "l"(b));
}

// ---------------- Kernel A: spectral norm scale ----------------------------
__global__ void sigma_kernel(const float* __restrict__ W,
                             const float* __restrict__ gamma,
                             const float* __restrict__ u) {
    __shared__ float sv[CC];
    __shared__ float red[CC];
    int c = threadIdx.x; // 64 threads

    float vt = 0.f;
    #pragma unroll 8
    for (int r = 0; r < CC; r++) vt += W[r * CC + c] * u[r];
    red[c] = vt * vt;
    __syncthreads();
    if (c == 0) {
        float s = 0.f;
        for (int i = 0; i < CC; i++) s += red[i];
        red[0] = 1.f / fmaxf(sqrtf(s), 1e-12f);
    }
    __syncthreads();
    float inv = red[0];
    sv[c] = vt * inv; // v
    __syncthreads();

    float wv = 0.f;
    #pragma unroll 8
    for (int k = 0; k < CC; k++) wv += W[c * CC + k] * sv[k];
    red[c] = wv * wv;
    __syncthreads();
    if (c == 0) {
        float s2 = 0.f;
        for (int i = 0; i < CC; i++) s2 += red[i];
        float sigma = s2 / fmaxf(sqrtf(s2), 1e-12f);
        g_scale = gamma[0] / sigma;
    }
}

// ---------------- Kernel B: partial Grams G[b] = xf xf^T --------------------
// grid (GCHUNKS, BB), 64 threads. Each thread owns 8 rows x (4+4) cols of the
// 64x64 Gram: cols [4tj..4tj+3] and [4tj+32..4tj+35]. Column loads are DENSE
// across the warp (16B stride) -> minimal LDS wavefronts.
__global__ void __launch_bounds__(64) gram_kernel(const float* __restrict__ x) {
    __shared__ float tile[KS][68];
    const int tid = threadIdx.x;
    const int b = blockIdx.y;
    const int chunk = blockIdx.x;
    const float* xb = x + (size_t)b * CC * NN + (size_t)chunk * GCN;

    const int ti = tid >> 3; // rows 8ti .. 8ti+7
    const int tj = tid & 7;  // cols 4tj..4tj+3 and 4tj+32..4tj+35

    unsigned long long acc[8][4];
    #pragma unroll
    for (int i = 0; i < 8; i++)
        #pragma unroll
        for (int j = 0; j < 4; j++) acc[i][j] = 0ull;

    for (int ks = 0; ks < GCN; ks += KS) {
        __syncthreads();
        // stage KS x 64 (transposed): tile[n][cc]
        #pragma unroll
        for (int l = 0; l < 16; l++) {
            int idx = tid + l * 64;    // 0..1023
            int n = idx & 15;
            int cc = idx >> 4;         // 0..63
            tile[n][cc] = xb[(size_t)cc * NN + ks + n];
        }
        __syncthreads();
        #pragma unroll 8
        for (int n = 0; n < KS; n++) {
            float4 r0 = *(const float4*)&tile[n][8 * ti];
            float4 r1 = *(const float4*)&tile[n][8 * ti + 4];
            ulonglong2 c0 = *(const ulonglong2*)&tile[n][4 * tj];      // dense
            ulonglong2 c1 = *(const ulonglong2*)&tile[n][4 * tj + 32]; // dense
            unsigned long long a0 = pk2(r0.x, r0.x);
            unsigned long long a1 = pk2(r0.y, r0.y);
            unsigned long long a2 = pk2(r0.z, r0.z);
            unsigned long long a3 = pk2(r0.w, r0.w);
            unsigned long long a4 = pk2(r1.x, r1.x);
            unsigned long long a5 = pk2(r1.y, r1.y);
            unsigned long long a6 = pk2(r1.z, r1.z);
            unsigned long long a7 = pk2(r1.w, r1.w);
            fma2(acc[0][0], a0, c0.x); fma2(acc[0][1], a0, c0.y);
            fma2(acc[0][2], a0, c1.x); fma2(acc[0][3], a0, c1.y);
            fma2(acc[1][0], a1, c0.x); fma2(acc[1][1], a1, c0.y);
            fma2(acc[1][2], a1, c1.x); fma2(acc[1][3], a1, c1.y);
            fma2(acc[2][0], a2, c0.x); fma2(acc[2][1], a2, c0.y);
            fma2(acc[2][2], a2, c1.x); fma2(acc[2][3], a2, c1.y);
            fma2(acc[3][0], a3, c0.x); fma2(acc[3][1], a3, c0.y);
            fma2(acc[3][2], a3, c1.x); fma2(acc[3][3], a3, c1.y);
            fma2(acc[4][0], a4, c0.x); fma2(acc[4][1], a4, c0.y);
            fma2(acc[4][2], a4, c1.x); fma2(acc[4][3], a4, c1.y);
            fma2(acc[5][0], a5, c0.x); fma2(acc[5][1], a5, c0.y);
            fma2(acc[5][2], a5, c1.x); fma2(acc[5][3], a5, c1.y);
            fma2(acc[6][0], a6, c0.x); fma2(acc[6][1], a6, c0.y);
            fma2(acc[6][2], a6, c1.x); fma2(acc[6][3], a6, c1.y);
            fma2(acc[7][0], a7, c0.x); fma2(acc[7][1], a7, c0.y);
            fma2(acc[7][2], a7, c1.x); fma2(acc[7][3], a7, c1.y);
        }
    }

    float* gp = g_partial + ((size_t)(b * GCHUNKS + chunk)) * CC * CC;
    #pragma unroll
    for (int i = 0; i < 8; i++) {
        float4 o0, o1;
        upk2(acc[i][0], o0.x, o0.y);
        upk2(acc[i][1], o0.z, o0.w);
        upk2(acc[i][2], o1.x, o1.y);
        upk2(acc[i][3], o1.z, o1.w);
        *(float4*)&gp[(8 * ti + i) * CC + 4 * tj]      = o0;
        *(float4*)&gp[(8 * ti + i) * CC + 4 * tj + 32] = o1;
    }
}

// ---------------- Kernel C: A[b] = (gamma/sigma) * G[b] * W -----------------
__global__ void __launch_bounds__(256) afuse_kernel(const float* __restrict__ W) {
    __shared__ float Gs[CC][68];
    __shared__ float Ws[CC][68];
    const int tid = threadIdx.x;
    const int b = blockIdx.x;
    const int ti = tid >> 4;
    const int tj = tid & 15;

    float g[4][4];
    #pragma unroll
    for (int ii = 0; ii < 4; ii++)
        #pragma unroll
        for (int jj = 0; jj < 4; jj++) g[ii][jj] = 0.f;

    for (int k = 0; k < GCHUNKS; k++) {
        const float* gp = g_partial + ((size_t)(b * GCHUNKS + k)) * CC * CC;
        #pragma unroll
        for (int ii = 0; ii < 4; ii++) {
            float4 v = *(const float4*)&gp[(4 * ti + ii) * CC + 4 * tj];
            g[ii][0] += v.x; g[ii][1] += v.y; g[ii][2] += v.z; g[ii][3] += v.w;
        }
    }
    #pragma unroll
    for (int ii = 0; ii < 4; ii++)
        #pragma unroll
        for (int jj = 0; jj < 4; jj++) Gs[4 * ti + ii][4 * tj + jj] = g[ii][jj];

    #pragma unroll
    for (int l = 0; l < 16; l++) {
        int idx = tid + l * 256; // 0..4095
        Ws[idx >> 6][idx & 63] = W[idx];
    }
    __syncthreads();

    float a[4][4];
    #pragma unroll
    for (int ii = 0; ii < 4; ii++)
        #pragma unroll
        for (int jj = 0; jj < 4; jj++) a[ii][jj] = 0.f;

    for (int k = 0; k < CC; k++) {
        float4 wv = *(const float4*)&Ws[k][4 * tj];
        float g0 = Gs[4 * ti + 0][k];
        float g1 = Gs[4 * ti + 1][k];
        float g2 = Gs[4 * ti + 2][k];
        float g3 = Gs[4 * ti + 3][k];
        a[0][0] += g0 * wv.x; a[0][1] += g0 * wv.y; a[0][2] += g0 * wv.z; a[0][3] += g0 * wv.w;
        a[1][0] += g1 * wv.x; a[1][1] += g1 * wv.y; a[1][2] += g1 * wv.z; a[1][3] += g1 * wv.w;
        a[2][0] += g2 * wv.x; a[2][1] += g2 * wv.y; a[2][2] += g2 * wv.z; a[2][3] += g2 * wv.w;
        a[3][0] += g3 * wv.x; a[3][1] += g3 * wv.y; a[3][2] += g3 * wv.z; a[3][3] += g3 * wv.w;
    }

    float s = g_scale;
    float* Ab = g_A + (size_t)b * CC * CC;
    #pragma unroll
    for (int ii = 0; ii < 4; ii++)
        #pragma unroll
        for (int jj = 0; jj < 4; jj++)
            Ab[(4 * ti + ii) * CC + 4 * tj + jj] = s * a[ii][jj];
}

// ---------------- Kernel D: out = A[b] @ xf + xf ----------------------------
// grid (NN/128, BB), 128 threads. Block tile 64 rows x 128 cols.
// Thread tile: 8 rows x (4+4) cols: [4tj..4tj+3] and [4tj+64..4tj+67].
// x-loads are DENSE across the 16 tj lanes (16B stride) -> 2 wavefronts each.
__global__ void __launch_bounds__(128) out_kernel(const float* __restrict__ x,
                                                  float* __restrict__ out) {
    __shared__ float As[CC][68];  // As[k][i] = A[i][k]
    __shared__ float xs[CC][132]; // xs[c][n], 128 cols + pad
    const int tid = threadIdx.x;
    const int b = blockIdx.y;
    const int n0 = blockIdx.x * 128;
    const float* xb = x + (size_t)b * CC * NN + n0;
    const float* Ab = g_A + (size_t)b * CC * CC;

    // load A transposed: 4096 floats / 128 threads = 32 each
    #pragma unroll
    for (int l = 0; l < 32; l++) {
        int idx = tid + l * 128; // 0..4095
        int i = idx >> 6;
        int c = idx & 63;
        As[c][i] = Ab[idx];
    }
    // load xs: 64 x 128 floats via float4 (2048 f4 / 128 threads = 16 each)
    #pragma unroll
    for (int l = 0; l < 16; l++) {
        int idx = tid + l * 128; // 0..2047
        int c = idx >> 5;        // 0..63
        int n4 = (idx & 31) * 4; // 0..124
        float4 v = *(const float4*)&xb[(size_t)c * NN + n4];
        *(float4*)&xs[c][n4] = v;
    }
    __syncthreads();

    const int ti = tid >> 4; // 0..7 -> rows 8ti..8ti+7
    const int tj = tid & 15; // 0..15 -> cols 4tj..4tj+3 and 4tj+64..+67

    unsigned long long acc[8][4];
    #pragma unroll
    for (int i = 0; i < 8; i++)
        #pragma unroll
        for (int j = 0; j < 4; j++) acc[i][j] = 0ull;

    #pragma unroll 8
    for (int k = 0; k < CC; k++) {
        float4 av0 = *(const float4*)&As[k][8 * ti];
        float4 av1 = *(const float4*)&As[k][8 * ti + 4];
        ulonglong2 x0 = *(const ulonglong2*)&xs[k][4 * tj];      // dense 256B
        ulonglong2 x1 = *(const ulonglong2*)&xs[k][4 * tj + 64]; // dense 256B
        unsigned long long a0 = pk2(av0.x, av0.x);
        unsigned long long a1 = pk2(av0.y, av0.y);
        unsigned long long a2 = pk2(av0.z, av0.z);
        unsigned long long a3 = pk2(av0.w, av0.w);
        unsigned long long a4 = pk2(av1.x, av1.x);
        unsigned long long a5 = pk2(av1.y, av1.y);
        unsigned long long a6 = pk2(av1.z, av1.z);
        unsigned long long a7 = pk2(av1.w, av1.w);
        fma2(acc[0][0], a0, x0.x); fma2(acc[0][1], a0, x0.y);
        fma2(acc[0][2], a0, x1.x); fma2(acc[0][3], a0, x1.y);
        fma2(acc[1][0], a1, x0.x); fma2(acc[1][1], a1, x0.y);
        fma2(acc[1][2], a1, x1.x); fma2(acc[1][3], a1, x1.y);
        fma2(acc[2][0], a2, x0.x); fma2(acc[2][1], a2, x0.y);
        fma2(acc[2][2], a2, x1.x); fma2(acc[2][3], a2, x1.y);
        fma2(acc[3][0], a3, x0.x); fma2(acc[3][1], a3, x0.y);
        fma2(acc[3][2], a3, x1.x); fma2(acc[3][3], a3, x1.y);
        fma2(acc[4][0], a4, x0.x); fma2(acc[4][1], a4, x0.y);
        fma2(acc[4][2], a4, x1.x); fma2(acc[4][3], a4, x1.y);
        fma2(acc[5][0], a5, x0.x); fma2(acc[5][1], a5, x0.y);
        fma2(acc[5][2], a5, x1.x); fma2(acc[5][3], a5, x1.y);
        fma2(acc[6][0], a6, x0.x); fma2(acc[6][1], a6, x0.y);
        fma2(acc[6][2], a6, x1.x); fma2(acc[6][3], a6, x1.y);
        fma2(acc[7][0], a7, x0.x); fma2(acc[7][1], a7, x0.y);
        fma2(acc[7][2], a7, x1.x); fma2(acc[7][3], a7, x1.y);
    }

    // epilogue: add residual x, store (dense float4 stores across lanes)
    #pragma unroll
    for (int i = 0; i < 8; i++) {
        int row = 8 * ti + i;
        float4 xa0 = *(const float4*)&xs[row][4 * tj];
        float4 xa1 = *(const float4*)&xs[row][4 * tj + 64];
        float4 o0, o1;
        upk2(acc[i][0], o0.x, o0.y);
        upk2(acc[i][1], o0.z, o0.w);
        upk2(acc[i][2], o1.x, o1.y);
        upk2(acc[i][3], o1.z, o1.w);
        o0.x += xa0.x; o0.y += xa0.y; o0.z += xa0.z; o0.w += xa0.w;
        o1.x += xa1.x; o1.y += xa1.y; o1.z += xa1.z; o1.w += xa1.w;
        float* op = out + (size_t)b * CC * NN + (size_t)row * NN + n0;
        *(float4*)&op[4 * tj]      = o0;
        *(float4*)&op[4 * tj + 64] = o1;
    }
}

// ---------------- launch ----------------------------------------------------
extern "C" void kernel_launch(void* const* d_in, const int* in_sizes, int n_in,
                              void* d_out, int out_size) {
    const float* x     = (const float*)d_in[0]; // [32,64,128,128]
    const float* W     = (const float*)d_in[1]; // [64,64]
    const float* gamma = (const float*)d_in[2]; // [1]
    const float* u     = (const float*)d_in[3]; // [64]
    float* out = (float*)d_out;

    sigma_kernel<<<1, 64>>>(W, gamma, u);

    dim3 gb(GCHUNKS, BB);
    gram_kernel<<<gb, 64>>>(x);

    afuse_kernel<<<BB, 256>>>(W);

    dim3 gd(NN / 128, BB);
    out_kernel<<<gd, 128>>>(x, out);
}

// round 8
// speedup vs baseline: 1.7806x; 1.3751x over previous
#include <cuda_runtime.h>
#include <cuda_bf16.h>
#include <cstdint>

// Problem constants
#define BB 32
#define CC 64
#define NN 16384
#define GCHUNKS 32
#define GCN 512            // NN / GCHUNKS

// ---------------- scratch (device globals; no allocation allowed) ----------
__device__ float g_partial[BB * GCHUNKS * CC * CC];       // partial Grams
__device__ __align__(16) unsigned short g_Ahi[BB * 4096]; // bf16 A images [c][d]
__device__ __align__(16) unsigned short g_Alo[BB * 4096];
__device__ float g_scale;                                 // gamma / sigma

// ---------------- helpers ---------------------------------------------------
__device__ __forceinline__ uint32_t smem_u32(const void* p) {
    uint32_t a;
    asm("{ .reg .u64 t; cvta.to.shared.u64 t, %1; cvt.u32.u64 %0, t; }"
        : "=r"(a) : "l"(p));
    return a;
}

__device__ __forceinline__ void ldsm4(uint32_t* r, uint32_t addr) {
    asm volatile("ldmatrix.sync.aligned.m8n8.x4.shared.b16 {%0,%1,%2,%3}, [%4];"
                 : "=r"(r[0]), "=r"(r[1]), "=r"(r[2]), "=r"(r[3]) : "r"(addr));
}
__device__ __forceinline__ void ldsm4t(uint32_t* r, uint32_t addr) {
    asm volatile("ldmatrix.sync.aligned.m8n8.x4.trans.shared.b16 {%0,%1,%2,%3}, [%4];"
                 : "=r"(r[0]), "=r"(r[1]), "=r"(r[2]), "=r"(r[3]) : "r"(addr));
}
__device__ __forceinline__ void mma16816(float* d, const uint32_t* a,
                                         uint32_t b0, uint32_t b1) {
    asm volatile(
        "mma.sync.aligned.m16n8k16.row.col.f32.bf16.bf16.f32 "
        "{%0,%1,%2,%3}, {%4,%5,%6,%7}, {%8,%9}, {%0,%1,%2,%3};"
        : "+f"(d[0]), "+f"(d[1]), "+f"(d[2]), "+f"(d[3])
        : "r"(a[0]), "r"(a[1]), "r"(a[2]), "r"(a[3]), "r"(b0), "r"(b1));
}

// split two f32 into packed bf16 hi-pair and lo-pair (truncation split:
// hi = upper 16 bits; lo = exact remainder truncated -> total err ~2^-16)
__device__ __forceinline__ void split2(float v0, float v1,
                                       uint32_t& hp, uint32_t& lp) {
    uint32_t b0 = __float_as_uint(v0), b1 = __float_as_uint(v1);
    hp = (b0 >> 16) | (b1 & 0xFFFF0000u);
    float l0 = v0 - __uint_as_float(b0 & 0xFFFF0000u);
    float l1 = v1 - __uint_as_float(b1 & 0xFFFF0000u);
    lp = (__float_as_uint(l0) >> 16) | (__float_as_uint(l1) & 0xFFFF0000u);
}

// ---------------- Kernel A: spectral norm scale ----------------------------
__global__ void sigma_kernel(const float* __restrict__ W,
                             const float* __restrict__ gamma,
                             const float* __restrict__ u) {
    __shared__ float sv[CC];
    __shared__ float red[CC];
    int c = threadIdx.x; // 64 threads

    float vt = 0.f;
    #pragma unroll 8
    for (int r = 0; r < CC; r++) vt += W[r * CC + c] * u[r];
    red[c] = vt * vt;
    __syncthreads();
    if (c == 0) {
        float s = 0.f;
        for (int i = 0; i < CC; i++) s += red[i];
        red[0] = 1.f / fmaxf(sqrtf(s), 1e-12f);
    }
    __syncthreads();
    float inv = red[0];
    sv[c] = vt * inv;
    __syncthreads();

    float wv = 0.f;
    #pragma unroll 8
    for (int k = 0; k < CC; k++) wv += W[c * CC + k] * sv[k];
    red[c] = wv * wv;
    __syncthreads();
    if (c == 0) {
        float s2 = 0.f;
        for (int i = 0; i < CC; i++) s2 += red[i];
        float sigma = s2 / fmaxf(sqrtf(s2), 1e-12f);
        g_scale = gamma[0] / sigma;
    }
}

// ---------------- Kernel B: Gram partials via HMMA (mma.sync) ---------------
// grid (GCHUNKS, BB), 128 threads (4 warps). D[m][n] = sum_k X[m][k] X[n][k]
// with both fragments loaded from the SAME channel-major smem tile.
// Warp w computes rows 16w..16w+15 x all 64 cols. bf16 split: hh + hl + lh.
__global__ void __launch_bounds__(128) gram_mma(const float* __restrict__ x) {
    __shared__ __align__(16) unsigned short hiT[64][72]; // [channel][k] bf16 hi
    __shared__ __align__(16) unsigned short loT[64][72]; // lo
    const int tid = threadIdx.x, warp = tid >> 5, lane = tid & 31;
    const int chunk = blockIdx.x, b = blockIdx.y;
    const float* xb = x + (size_t)b * CC * NN + (size_t)chunk * GCN;

    float acc[8][4];
    #pragma unroll
    for (int i = 0; i < 8; i++)
        #pragma unroll
        for (int j = 0; j < 4; j++) acc[i][j] = 0.f;

    const int mat = lane >> 3, mr = lane & 7; // ldmatrix x4 lane roles

    for (int s = 0; s < 8; s++) { // 8 stages of 64 k
        __syncthreads();
        #pragma unroll
        for (int k = 0; k < 8; k++) {
            int e = tid + k * 128;     // 0..1023
            int c = e >> 4;            // channel 0..63
            int k4 = (e & 15) * 4;     // k offset 0..60
            float4 v = *(const float4*)&xb[(size_t)c * NN + s * 64 + k4];
            uint32_t h0, l0, h1, l1;
            split2(v.x, v.y, h0, l0);
            split2(v.z, v.w, h1, l1);
            *(uint2*)&hiT[c][k4] = make_uint2(h0, h1);
            *(uint2*)&loT[c][k4] = make_uint2(l0, l1);
        }
        __syncthreads();
        #pragma unroll
        for (int ks = 0; ks < 4; ks++) { // k16 steps within stage
            uint32_t ah[4], al[4];
            int arow = 16 * warp + ((mat & 1) << 3) + mr;
            int acol = ks * 16 + ((mat >> 1) << 3);
            ldsm4(ah, smem_u32(&hiT[arow][acol]));
            ldsm4(al, smem_u32(&loT[arow][acol]));
            #pragma unroll
            for (int g = 0; g < 4; g++) { // 4 x (two n8 groups)
                uint32_t bh[4], bl[4];
                int brow = 16 * g + ((mat & 1) << 3) + mr;
                ldsm4(bh, smem_u32(&hiT[brow][acol]));
                ldsm4(bl, smem_u32(&loT[brow][acol]));
                mma16816(acc[2 * g],     ah, bh[0], bh[2]);
                mma16816(acc[2 * g],     ah, bl[0], bl[2]);
                mma16816(acc[2 * g],     al, bh[0], bh[2]);
                mma16816(acc[2 * g + 1], ah, bh[1], bh[3]);
                mma16816(acc[2 * g + 1], ah, bl[1], bl[3]);
                mma16816(acc[2 * g + 1], al, bh[1], bh[3]);
            }
        }
    }

    // epilogue: D-frag -> g_partial[b][chunk][row][col]
    float* gp = g_partial + ((size_t)b * GCHUNKS + chunk) * 4096;
    int r0 = 16 * warp + (lane >> 2), c0 = (lane & 3) * 2;
    #pragma unroll
    for (int j = 0; j < 8; j++) {
        *(float2*)&gp[r0 * 64 + 8 * j + c0]       = make_float2(acc[j][0], acc[j][1]);
        *(float2*)&gp[(r0 + 8) * 64 + 8 * j + c0] = make_float2(acc[j][2], acc[j][3]);
    }
}

// ---------------- Kernel C: A = (gamma/sigma) * G * W -> bf16 hi/lo images --
// grid (4 slices, BB), 256 threads. Slice = 16 rows of A. Output row-major
// [c][d] bf16 hi/lo for out_mma's ldmatrix fragment loads.
__global__ void __launch_bounds__(256) afuse_kernel(const float* __restrict__ W) {
    __shared__ float Gs[16][68];
    __shared__ float Ws[CC][68];
    const int tid = threadIdx.x;
    const int slice = blockIdx.x; // 0..3
    const int b = blockIdx.y;     // 0..31
    const int row_l = tid >> 4;       // 0..15
    const int c4 = (tid & 15) * 4;    // col base

    float4 acc = make_float4(0.f, 0.f, 0.f, 0.f);
    for (int k = 0; k < GCHUNKS; k++) {
        const float* gp = g_partial + ((size_t)b * GCHUNKS + k) * 4096
                          + (slice * 16 + row_l) * 64 + c4;
        float4 v = *(const float4*)gp;
        acc.x += v.x; acc.y += v.y; acc.z += v.z; acc.w += v.w;
    }
    *(float4*)&Gs[row_l][c4] = acc;

    #pragma unroll
    for (int l = 0; l < 16; l++) {
        int idx = tid + l * 256; // 0..4095
        Ws[idx >> 6][idx & 63] = W[idx];
    }
    __syncthreads();

    float a0 = 0.f, a1 = 0.f, a2 = 0.f, a3 = 0.f;
    #pragma unroll 8
    for (int k = 0; k < CC; k++) {
        float g = Gs[row_l][k];
        float4 w = *(const float4*)&Ws[k][c4];
        a0 += g * w.x; a1 += g * w.y; a2 += g * w.z; a3 += g * w.w;
    }

    float s = g_scale;
    int grow = slice * 16 + row_l;
    uint32_t hp0, lp0, hp1, lp1;
    split2(s * a0, s * a1, hp0, lp0);
    split2(s * a2, s * a3, hp1, lp1);
    size_t off = (size_t)b * 4096 + grow * 64 + c4;
    *(uint2*)&g_Ahi[off] = make_uint2(hp0, hp1);
    *(uint2*)&g_Alo[off] = make_uint2(lp0, lp1);
}

// ---------------- Kernel D: out = A @ x + x via HMMA ------------------------
// grid (128 nblk, BB), 128 threads. Tile: 64 c x 128 n. B = x[d][n] staged in
// natural layout; fragments via ldmatrix.trans. Residual f32 re-read (L1-hot).
#define OUT_SMEM 53248
__global__ void __launch_bounds__(128) out_mma(const float* __restrict__ x,
                                               float* __restrict__ out) {
    extern __shared__ __align__(16) unsigned char sm[];
    typedef unsigned short (*arr72)[72];
    typedef unsigned short (*arr136)[136];
    arr72 Ah  = (arr72)(sm);                   //  9216 B
    arr72 Al  = (arr72)(sm + 9216);            //  9216 B
    arr136 Bh = (arr136)(sm + 18432);          // 17408 B
    arr136 Bl = (arr136)(sm + 18432 + 17408);  // 17408 B

    const int tid = threadIdx.x, warp = tid >> 5, lane = tid & 31;
    const int nblk = blockIdx.x, b = blockIdx.y;
    const float* xb = x + (size_t)b * CC * NN + (size_t)nblk * 128;
    float* ob = out + (size_t)b * CC * NN + (size_t)nblk * 128;

    // stage A images (already bf16, row-major [c][d])
    const uint4* AhG = (const uint4*)(g_Ahi + (size_t)b * 4096);
    const uint4* AlG = (const uint4*)(g_Alo + (size_t)b * 4096);
    #pragma unroll
    for (int k = 0; k < 4; k++) {
        int e = tid + k * 128;       // 0..511
        int c = e >> 3, d8 = (e & 7) * 8;
        *(uint4*)&Ah[c][d8] = AhG[e];
        *(uint4*)&Al[c][d8] = AlG[e];
    }
    // stage B: x[d][n] f32 -> bf16 hi/lo, natural layout (coalesced)
    #pragma unroll
    for (int k = 0; k < 16; k++) {
        int e = tid + k * 128;       // 0..2047
        int d = e >> 5, n4 = (e & 31) * 4;
        float4 v = *(const float4*)&xb[(size_t)d * NN + n4];
        uint32_t h0, l0, h1, l1;
        split2(v.x, v.y, h0, l0);
        split2(v.z, v.w, h1, l1);
        *(uint2*)&Bh[d][n4] = make_uint2(h0, h1);
        *(uint2*)&Bl[d][n4] = make_uint2(l0, l1);
    }
    __syncthreads();

    float acc[16][4];
    #pragma unroll
    for (int i = 0; i < 16; i++)
        #pragma unroll
        for (int j = 0; j < 4; j++) acc[i][j] = 0.f;

    const int mat = lane >> 3, mr = lane & 7;
    #pragma unroll
    for (int ks = 0; ks < 4; ks++) { // k = d, 4 x 16
        uint32_t ah[4], al[4];
        int arow = 16 * warp + ((mat & 1) << 3) + mr;
        int acol = ks * 16 + ((mat >> 1) << 3);
        ldsm4(ah, smem_u32(&Ah[arow][acol]));
        ldsm4(al, smem_u32(&Al[arow][acol]));
        #pragma unroll
        for (int g = 0; g < 8; g++) { // 8 x (two n8 groups)
            uint32_t bh[4], bl[4];
            int drow = ks * 16 + ((mat & 1) << 3) + mr;
            int ncol = 16 * g + ((mat >> 1) << 3);
            ldsm4t(bh, smem_u32(&Bh[drow][ncol]));
            ldsm4t(bl, smem_u32(&Bl[drow][ncol]));
            mma16816(acc[2 * g],     ah, bh[0], bh[1]);
            mma16816(acc[2 * g],     ah, bl[0], bl[1]);
            mma16816(acc[2 * g],     al, bh[0], bh[1]);
            mma16816(acc[2 * g + 1], ah, bh[2], bh[3]);
            mma16816(acc[2 * g + 1], ah, bl[2], bl[3]);
            mma16816(acc[2 * g + 1], al, bh[2], bh[3]);
        }
    }

    // epilogue: residual add (exact f32 from global, L1-hot) + store
    int c0 = 16 * warp + (lane >> 2), t2 = (lane & 3) * 2;
    #pragma unroll
    for (int g = 0; g < 16; g++) {
        int col = 8 * g + t2;
        float2 x0 = *(const float2*)&xb[(size_t)c0 * NN + col];
        float2 x1 = *(const float2*)&xb[(size_t)(c0 + 8) * NN + col];
        *(float2*)&ob[(size_t)c0 * NN + col] =
            make_float2(acc[g][0] + x0.x, acc[g][1] + x0.y);
        *(float2*)&ob[(size_t)(c0 + 8) * NN + col] =
            make_float2(acc[g][2] + x1.x, acc[g][3] + x1.y);
    }
}

// ---------------- launch ----------------------------------------------------
extern "C" void kernel_launch(void* const* d_in, const int* in_sizes, int n_in,
                              void* d_out, int out_size) {
    const float* x     = (const float*)d_in[0]; // [32,64,128,128]
    const float* W     = (const float*)d_in[1]; // [64,64]
    const float* gamma = (const float*)d_in[2]; // [1]
    const float* u     = (const float*)d_in[3]; // [64]
    float* out = (float*)d_out;

    cudaFuncSetAttribute(out_mma, cudaFuncAttributeMaxDynamicSharedMemorySize,
                         OUT_SMEM);

    sigma_kernel<<<1, 64>>>(W, gamma, u);

    dim3 gg(GCHUNKS, BB);
    gram_mma<<<gg, 128>>>(x);

    dim3 ga(4, BB);
    afuse_kernel<<<ga, 256>>>(W);

    dim3 go(NN / 128, BB);
    out_mma<<<go, 128, OUT_SMEM>>>(x, out);
}

// round 9
// speedup vs baseline: 1.9124x; 1.0740x over previous
#include <cuda_runtime.h>
#include <cuda_bf16.h>
#include <cstdint>

// Problem constants
#define BB 32
#define CC 64
#define NN 16384
#define GCHUNKS 32
#define GCN 512            // NN / GCHUNKS

// ---------------- scratch (device globals; no allocation allowed) ----------
__device__ float g_partial[BB * GCHUNKS * CC * CC];       // partial Grams
__device__ __align__(16) unsigned short g_Ahi[BB * 4096]; // bf16 A images [c][d]
__device__ __align__(16) unsigned short g_Alo[BB * 4096];
__device__ float g_scale;                                 // gamma / sigma

// ---------------- helpers ---------------------------------------------------
__device__ __forceinline__ uint32_t smem_u32(const void* p) {
    uint32_t a;
    asm("{ .reg .u64 t; cvta.to.shared.u64 t, %1; cvt.u32.u64 %0, t; }"
        : "=r"(a) : "l"(p));
    return a;
}

__device__ __forceinline__ void ldsm4(uint32_t* r, uint32_t addr) {
    asm volatile("ldmatrix.sync.aligned.m8n8.x4.shared.b16 {%0,%1,%2,%3}, [%4];"
                 : "=r"(r[0]), "=r"(r[1]), "=r"(r[2]), "=r"(r[3]) : "r"(addr));
}
__device__ __forceinline__ void ldsm4t(uint32_t* r, uint32_t addr) {
    asm volatile("ldmatrix.sync.aligned.m8n8.x4.trans.shared.b16 {%0,%1,%2,%3}, [%4];"
                 : "=r"(r[0]), "=r"(r[1]), "=r"(r[2]), "=r"(r[3]) : "r"(addr));
}
__device__ __forceinline__ void mma16816(float* d, const uint32_t* a,
                                         uint32_t b0, uint32_t b1) {
    asm volatile(
        "mma.sync.aligned.m16n8k16.row.col.f32.bf16.bf16.f32 "
        "{%0,%1,%2,%3}, {%4,%5,%6,%7}, {%8,%9}, {%0,%1,%2,%3};"
        : "+f"(d[0]), "+f"(d[1]), "+f"(d[2]), "+f"(d[3])
        : "r"(a[0]), "r"(a[1]), "r"(a[2]), "r"(a[3]), "r"(b0), "r"(b1));
}

// split two f32 into packed bf16 hi-pair and lo-pair (truncation split:
// hi = upper 16 bits; lo = exact remainder truncated -> total err ~2^-16)
__device__ __forceinline__ void split2(float v0, float v1,
                                       uint32_t& hp, uint32_t& lp) {
    uint32_t b0 = __float_as_uint(v0), b1 = __float_as_uint(v1);
    hp = (b0 >> 16) | (b1 & 0xFFFF0000u);
    float l0 = v0 - __uint_as_float(b0 & 0xFFFF0000u);
    float l1 = v1 - __uint_as_float(b1 & 0xFFFF0000u);
    lp = (__float_as_uint(l0) >> 16) | (__float_as_uint(l1) & 0xFFFF0000u);
}

// ---------------- Kernel A: spectral norm scale ----------------------------
__global__ void sigma_kernel(const float* __restrict__ W,
                             const float* __restrict__ gamma,
                             const float* __restrict__ u) {
    __shared__ float sv[CC];
    __shared__ float red[CC];
    int c = threadIdx.x; // 64 threads

    float vt = 0.f;
    #pragma unroll 8
    for (int r = 0; r < CC; r++) vt += W[r * CC + c] * u[r];
    red[c] = vt * vt;
    __syncthreads();
    if (c == 0) {
        float s = 0.f;
        for (int i = 0; i < CC; i++) s += red[i];
        red[0] = 1.f / fmaxf(sqrtf(s), 1e-12f);
    }
    __syncthreads();
    float inv = red[0];
    sv[c] = vt * inv;
    __syncthreads();

    float wv = 0.f;
    #pragma unroll 8
    for (int k = 0; k < CC; k++) wv += W[c * CC + k] * sv[k];
    red[c] = wv * wv;
    __syncthreads();
    if (c == 0) {
        float s2 = 0.f;
        for (int i = 0; i < CC; i++) s2 += red[i];
        float sigma = s2 / fmaxf(sqrtf(s2), 1e-12f);
        g_scale = gamma[0] / sigma;
    }
}

// ---------------- Kernel B: Gram partials via HMMA (mma.sync) ---------------
// grid (GCHUNKS, BB), 256 threads (8 warps: 4 M-slices x 2 N-halves).
// D[m][n] = sum_k X[m][k] X[n][k], both fragments from the same smem tile.
// Warp (wm, wn) computes rows 16wm..+15 x cols 32wn..+31.
__global__ void __launch_bounds__(256) gram_mma(const float* __restrict__ x) {
    __shared__ __align__(16) unsigned short hiT[64][72]; // [channel][k] bf16 hi
    __shared__ __align__(16) unsigned short loT[64][72]; // lo
    const int tid = threadIdx.x, warp = tid >> 5, lane = tid & 31;
    const int wm = warp & 3, wn = warp >> 2;
    const int chunk = blockIdx.x, b = blockIdx.y;
    const float* xb = x + (size_t)b * CC * NN + (size_t)chunk * GCN;

    float acc[4][4];
    #pragma unroll
    for (int i = 0; i < 4; i++)
        #pragma unroll
        for (int j = 0; j < 4; j++) acc[i][j] = 0.f;

    const int mat = lane >> 3, mr = lane & 7; // ldmatrix x4 lane roles

    for (int s = 0; s < 8; s++) { // 8 stages of 64 k
        __syncthreads();
        #pragma unroll
        for (int k = 0; k < 4; k++) {
            int e = tid + k * 256;     // 0..1023
            int c = e >> 4;            // channel 0..63
            int k4 = (e & 15) * 4;     // k offset 0..60
            float4 v = *(const float4*)&xb[(size_t)c * NN + s * 64 + k4];
            uint32_t h0, l0, h1, l1;
            split2(v.x, v.y, h0, l0);
            split2(v.z, v.w, h1, l1);
            *(uint2*)&hiT[c][k4] = make_uint2(h0, h1);
            *(uint2*)&loT[c][k4] = make_uint2(l0, l1);
        }
        __syncthreads();
        #pragma unroll
        for (int ks = 0; ks < 4; ks++) { // k16 steps within stage
            uint32_t ah[4], al[4];
            int arow = 16 * wm + ((mat & 1) << 3) + mr;
            int acol = ks * 16 + ((mat >> 1) << 3);
            ldsm4(ah, smem_u32(&hiT[arow][acol]));
            ldsm4(al, smem_u32(&loT[arow][acol]));
            #pragma unroll
            for (int g = 0; g < 2; g++) { // two 16-col groups in this half
                uint32_t bh[4], bl[4];
                int brow = 32 * wn + 16 * g + ((mat & 1) << 3) + mr;
                ldsm4(bh, smem_u32(&hiT[brow][acol]));
                ldsm4(bl, smem_u32(&loT[brow][acol]));
                mma16816(acc[2 * g],     ah, bh[0], bh[2]);
                mma16816(acc[2 * g],     ah, bl[0], bl[2]);
                mma16816(acc[2 * g],     al, bh[0], bh[2]);
                mma16816(acc[2 * g + 1], ah, bh[1], bh[3]);
                mma16816(acc[2 * g + 1], ah, bl[1], bl[3]);
                mma16816(acc[2 * g + 1], al, bh[1], bh[3]);
            }
        }
    }

    // epilogue: D-frag -> g_partial[b][chunk][row][col]
    float* gp = g_partial + ((size_t)b * GCHUNKS + chunk) * 4096;
    int r0 = 16 * wm + (lane >> 2), c0 = 32 * wn + (lane & 3) * 2;
    #pragma unroll
    for (int j = 0; j < 4; j++) {
        *(float2*)&gp[r0 * 64 + 8 * j + c0]       = make_float2(acc[j][0], acc[j][1]);
        *(float2*)&gp[(r0 + 8) * 64 + 8 * j + c0] = make_float2(acc[j][2], acc[j][3]);
    }
}

// ---------------- Kernel C: A = (gamma/sigma) * G * W -> bf16 hi/lo images --
// grid (4 slices, BB), 256 threads. Slice = 16 rows of A. Output row-major
// [c][d] bf16 hi/lo for out_mma's ldmatrix fragment loads.
__global__ void __launch_bounds__(256) afuse_kernel(const float* __restrict__ W) {
    __shared__ float Gs[16][68];
    __shared__ float Ws[CC][68];
    const int tid = threadIdx.x;
    const int slice = blockIdx.x; // 0..3
    const int b = blockIdx.y;     // 0..31
    const int row_l = tid >> 4;       // 0..15
    const int c4 = (tid & 15) * 4;    // col base

    float4 acc = make_float4(0.f, 0.f, 0.f, 0.f);
    for (int k = 0; k < GCHUNKS; k++) {
        const float* gp = g_partial + ((size_t)b * GCHUNKS + k) * 4096
                          + (slice * 16 + row_l) * 64 + c4;
        float4 v = *(const float4*)gp;
        acc.x += v.x; acc.y += v.y; acc.z += v.z; acc.w += v.w;
    }
    *(float4*)&Gs[row_l][c4] = acc;

    #pragma unroll
    for (int l = 0; l < 16; l++) {
        int idx = tid + l * 256; // 0..4095
        Ws[idx >> 6][idx & 63] = W[idx];
    }
    __syncthreads();

    float a0 = 0.f, a1 = 0.f, a2 = 0.f, a3 = 0.f;
    #pragma unroll 8
    for (int k = 0; k < CC; k++) {
        float g = Gs[row_l][k];
        float4 w = *(const float4*)&Ws[k][c4];
        a0 += g * w.x; a1 += g * w.y; a2 += g * w.z; a3 += g * w.w;
    }

    float s = g_scale;
    int grow = slice * 16 + row_l;
    uint32_t hp0, lp0, hp1, lp1;
    split2(s * a0, s * a1, hp0, lp0);
    split2(s * a2, s * a3, hp1, lp1);
    size_t off = (size_t)b * 4096 + grow * 64 + c4;
    *(uint2*)&g_Ahi[off] = make_uint2(hp0, hp1);
    *(uint2*)&g_Alo[off] = make_uint2(lp0, lp1);
}

// ---------------- Kernel D: out = A @ x + x via HMMA ------------------------
// grid (128 nblk, BB), 256 threads (8 warps: 4 M-slices x 2 N-halves).
// Tile: 64 c x 128 n. Warp (wm, wn): rows 16wm..+15, cols 64wn..+63.
// B = x[d][n] staged naturally; fragments via ldmatrix.trans.
#define OUT_SMEM 53248
__global__ void __launch_bounds__(256) out_mma(const float* __restrict__ x,
                                               float* __restrict__ out) {
    extern __shared__ __align__(16) unsigned char sm[];
    typedef unsigned short (*arr72)[72];
    typedef unsigned short (*arr136)[136];
    arr72 Ah  = (arr72)(sm);                   //  9216 B
    arr72 Al  = (arr72)(sm + 9216);            //  9216 B
    arr136 Bh = (arr136)(sm + 18432);          // 17408 B
    arr136 Bl = (arr136)(sm + 18432 + 17408);  // 17408 B

    const int tid = threadIdx.x, warp = tid >> 5, lane = tid & 31;
    const int wm = warp & 3, wn = warp >> 2;
    const int nblk = blockIdx.x, b = blockIdx.y;
    const float* xb = x + (size_t)b * CC * NN + (size_t)nblk * 128;
    float* ob = out + (size_t)b * CC * NN + (size_t)nblk * 128;

    // stage A images (already bf16, row-major [c][d])
    const uint4* AhG = (const uint4*)(g_Ahi + (size_t)b * 4096);
    const uint4* AlG = (const uint4*)(g_Alo + (size_t)b * 4096);
    #pragma unroll
    for (int k = 0; k < 2; k++) {
        int e = tid + k * 256;       // 0..511
        int c = e >> 3, d8 = (e & 7) * 8;
        *(uint4*)&Ah[c][d8] = AhG[e];
        *(uint4*)&Al[c][d8] = AlG[e];
    }
    // stage B: x[d][n] f32 -> bf16 hi/lo, natural layout (coalesced)
    #pragma unroll
    for (int k = 0; k < 8; k++) {
        int e = tid + k * 256;       // 0..2047
        int d = e >> 5, n4 = (e & 31) * 4;
        float4 v = *(const float4*)&xb[(size_t)d * NN + n4];
        uint32_t h0, l0, h1, l1;
        split2(v.x, v.y, h0, l0);
        split2(v.z, v.w, h1, l1);
        *(uint2*)&Bh[d][n4] = make_uint2(h0, h1);
        *(uint2*)&Bl[d][n4] = make_uint2(l0, l1);
    }
    __syncthreads();

    float acc[8][4];
    #pragma unroll
    for (int i = 0; i < 8; i++)
        #pragma unroll
        for (int j = 0; j < 4; j++) acc[i][j] = 0.f;

    const int mat = lane >> 3, mr = lane & 7;
    #pragma unroll
    for (int ks = 0; ks < 4; ks++) { // k = d, 4 x 16
        uint32_t ah[4], al[4];
        int arow = 16 * wm + ((mat & 1) << 3) + mr;
        int acol = ks * 16 + ((mat >> 1) << 3);
        ldsm4(ah, smem_u32(&Ah[arow][acol]));
        ldsm4(al, smem_u32(&Al[arow][acol]));
        #pragma unroll
        for (int g = 0; g < 4; g++) { // four 16-col groups in this half
            uint32_t bh[4], bl[4];
            int drow = ks * 16 + ((mat & 1) << 3) + mr;
            int ncol = 64 * wn + 16 * g + ((mat >> 1) << 3);
            ldsm4t(bh, smem_u32(&Bh[drow][ncol]));
            ldsm4t(bl, smem_u32(&Bl[drow][ncol]));
            mma16816(acc[2 * g],     ah, bh[0], bh[1]);
            mma16816(acc[2 * g],     ah, bl[0], bl[1]);
            mma16816(acc[2 * g],     al, bh[0], bh[1]);
            mma16816(acc[2 * g + 1], ah, bh[2], bh[3]);
            mma16816(acc[2 * g + 1], ah, bl[2], bl[3]);
            mma16816(acc[2 * g + 1], al, bh[2], bh[3]);
        }
    }

    // epilogue: residual add (exact f32 from global, L1-hot) + store
    int c0 = 16 * wm + (lane >> 2), t2 = (lane & 3) * 2;
    #pragma unroll
    for (int g = 0; g < 8; g++) {
        int col = 64 * wn + 8 * g + t2;
        float2 x0 = *(const float2*)&xb[(size_t)c0 * NN + col];
        float2 x1 = *(const float2*)&xb[(size_t)(c0 + 8) * NN + col];
        *(float2*)&ob[(size_t)c0 * NN + col] =
            make_float2(acc[g][0] + x0.x, acc[g][1] + x0.y);
        *(float2*)&ob[(size_t)(c0 + 8) * NN + col] =
            make_float2(acc[g][2] + x1.x, acc[g][3] + x1.y);
    }
}

// ---------------- launch ----------------------------------------------------
extern "C" void kernel_launch(void* const* d_in, const int* in_sizes, int n_in,
                              void* d_out, int out_size) {
    const float* x     = (const float*)d_in[0]; // [32,64,128,128]
    const float* W     = (const float*)d_in[1]; // [64,64]
    const float* gamma = (const float*)d_in[2]; // [1]
    const float* u     = (const float*)d_in[3]; // [64]
    float* out = (float*)d_out;

    cudaFuncSetAttribute(out_mma, cudaFuncAttributeMaxDynamicSharedMemorySize,
                         OUT_SMEM);

    sigma_kernel<<<1, 64>>>(W, gamma, u);

    dim3 gg(GCHUNKS, BB);
    gram_mma<<<gg, 256>>>(x);

    dim3 ga(4, BB);
    afuse_kernel<<<ga, 256>>>(W);

    dim3 go(NN / 128, BB);
    out_mma<<<go, 256, OUT_SMEM>>>(x, out);
}